// round 13
// baseline (speedup 1.0000x reference)
#include <cuda_runtime.h>
#include <cuda_bf16.h>

// preds:   (16, 19, 512, 512) float32  = 79,691,776 elems
// targets: (16, 1024, 1024)   labels in [0,19) (delivered as int32)
// grid_size = 16 -> 32x32 cells per batch, 16x16 px each
//
// k_presence: R12 verbatim (warp per 2 cells, MLP=8).
// k_loss: R12 math/indexing, but preds are streamed through a 6-stage
//         cp.async.cg pipeline (per-thread private smem slots, no barriers)
//         to lift loads-in-flight beyond the LDG scoreboard window.
// k_final: R12 verbatim.

#define N_ELEMS   79691776
#define N4        (N_ELEMS / 4)          // 19,922,944 float4s
#define N_CELLS   16384
#define LOSS_BLOCKS  2048
#define LOSS_THREADS 256
#define LOSS_STRIDE  (LOSS_BLOCKS * LOSS_THREADS)   // N4/STRIDE = 38 exactly
#define LOSS_ITERS   38
#define STAGES       6                   // 6 * 256 * 16B = 24 KB smem

__device__ unsigned g_masks[N_CELLS];
__device__ double   g_partial[LOSS_BLOCKS];

__device__ __forceinline__ float ex2_(float x) { float r; asm("ex2.approx.f32 %0, %1;" : "=f"(r) : "f"(x)); return r; }
__device__ __forceinline__ float lg2_(float x) { float r; asm("lg2.approx.f32 %0, %1;" : "=f"(r) : "f"(x)); return r; }

__device__ __forceinline__ unsigned smem_u32(const void* p) {
    unsigned a;
    asm("{ .reg .u64 t; cvta.to.shared.u64 t, %1; cvt.u32.u64 %0, t; }" : "=r"(a) : "l"(p));
    return a;
}
__device__ __forceinline__ void cp16(unsigned saddr, const void* g) {
    asm volatile("cp.async.cg.shared.global [%0], [%1], 16;" :: "r"(saddr), "l"(g) : "memory");
}
__device__ __forceinline__ void cp_commit() {
    asm volatile("cp.async.commit_group;" ::: "memory");
}
template <int N>
__device__ __forceinline__ void cp_wait() {
    asm volatile("cp.async.wait_group %0;" :: "n"(N) : "memory");
}

// ---------------------------------------------------------------------------
// Kernel 1: per-cell class-presence bitmask (stride-2 NN downsample).
// ---------------------------------------------------------------------------
__global__ void __launch_bounds__(256) k_presence(const int4* __restrict__ t4) {
    int gwarp = (blockIdx.x * blockDim.x + threadIdx.x) >> 5;  // 0..8191
    int lane  = threadIdx.x & 31;
    int cellA = gwarp << 1;
    int bA    = cellA >> 10;
    int restA = cellA & 1023;
    int chA   = restA >> 5;
    int cwA   = restA & 31;

    int baseA = (bA << 18) + (chA << 13) + (cwA << 3);
    int baseB = baseA + 8;

    int4 qa[4], qb[4];
#pragma unroll
    for (int k = 0; k < 4; ++k) {
        int e = lane + (k << 5);
        int i = e >> 3, jj = e & 7;
        int roff = (i << 9) + jj;
        qa[k] = __ldg(&t4[baseA + roff]);
        qb[k] = __ldg(&t4[baseB + roff]);
    }
    unsigned mA = 0, mB = 0;
#pragma unroll
    for (int k = 0; k < 4; ++k) {
        mA |= (1u << (qa[k].x & 31)) | (1u << (qa[k].z & 31));
        mB |= (1u << (qb[k].x & 31)) | (1u << (qb[k].z & 31));
    }
    mA = __reduce_or_sync(0xFFFFFFFFu, mA);
    mB = __reduce_or_sync(0xFFFFFFFFu, mB);
    if (lane == 0) { g_masks[cellA] = mA; g_masks[cellA + 1] = mB; }
}

// BCE element: al += lg2(1+e^{-|x|}); aa += relu(se ? -x : x)
__device__ __forceinline__ void bce_acc(float x, unsigned sgn, float& al, float& aa) {
    float t = ex2_(fabsf(x) * -1.4426950408889634f);
    al += lg2_(1.0f + t);
    float y = __int_as_float(__float_as_int(x) ^ sgn);
    aa += fmaxf(y, 0.0f);
}

// ---------------------------------------------------------------------------
// Kernel 2: streaming loss via cp.async pipeline (per-thread private slots).
// ---------------------------------------------------------------------------
__global__ void __launch_bounds__(LOSS_THREADS) k_loss(const float4* __restrict__ p4) {
    __shared__ __align__(16) float4 buf[STAGES][LOSS_THREADS];

    const int tid  = threadIdx.x;
    const int gtid = blockIdx.x * LOSS_THREADS + tid;

    int lin = gtid << 2;
    int w   = lin & 511;
    int h   = (lin >> 9) & 511;
    int cellhw = ((h >> 4) << 5) + (w >> 4);   // loop-invariant
    int bc0 = lin >> 18;                       // b*19+c at iter 0; +8 per iter

    const unsigned s0 = smem_u32(&buf[0][tid]);   // this thread's stage-0 slot
    const unsigned SLOT_STRIDE = LOSS_THREADS * 16;

    // prologue: prefetch iters 0..STAGES-2, one commit group each
#pragma unroll
    for (int s = 0; s < STAGES - 1; ++s) {
        cp16(s0 + s * SLOT_STRIDE, p4 + gtid + s * LOSS_STRIDE);
        cp_commit();
    }

    float al0 = 0.f, al1 = 0.f, aa0 = 0.f, aa1 = 0.f;
    int slot = 0;                                // consume slot index
    unsigned pf = s0 + (STAGES - 1) * SLOT_STRIDE;  // prefetch slot addr

#pragma unroll 2
    for (int k = 0; k < LOSS_ITERS; ++k) {
        // prefetch iter k+STAGES-1 (empty commit keeps group count uniform)
        if (k < LOSS_ITERS - (STAGES - 1)) {
            cp16(pf, p4 + gtid + (k + STAGES - 1) * LOSS_STRIDE);
            pf += SLOT_STRIDE;
            if (pf == s0 + STAGES * SLOT_STRIDE) pf = s0;
        }
        cp_commit();
        cp_wait<STAGES - 1>();                   // copy for iter k complete

        float4 v = buf[slot][tid];               // LDS.128, private slot
        if (++slot == STAGES) slot = 0;

        int bc = bc0 + (k << 3);
        int b  = bc / 19;
        int c  = bc - b * 19;
        unsigned mask = g_masks[(b << 10) + cellhw];
        unsigned sgn  = ((mask >> c) & 1u) << 31;
        bce_acc(v.x, sgn, al0, aa0);
        bce_acc(v.y, sgn, al1, aa1);
        bce_acc(v.z, sgn, al0, aa0);
        bce_acc(v.w, sgn, al1, aa1);
    }

    double acc = (double)(al0 + al1) * 0.6931471805599453 + (double)(aa0 + aa1);

    // deterministic block reduction
    __shared__ double smem[LOSS_THREADS / 32];
    for (int o = 16; o > 0; o >>= 1) acc += __shfl_down_sync(0xFFFFFFFFu, acc, o);
    if ((threadIdx.x & 31) == 0) smem[threadIdx.x >> 5] = acc;
    __syncthreads();
    if (threadIdx.x < (LOSS_THREADS / 32)) {
        double a = smem[threadIdx.x];
        for (int o = (LOSS_THREADS / 64); o > 0; o >>= 1)
            a += __shfl_down_sync(0xFFu, a, o);
        if (threadIdx.x == 0) g_partial[blockIdx.x] = a;
    }
}

// ---------------------------------------------------------------------------
// Kernel 3: final deterministic reduction -> mean.
// ---------------------------------------------------------------------------
__global__ void __launch_bounds__(256) k_final(float* __restrict__ out) {
    __shared__ double smem[8];
    double a = 0.0;
    for (int i = threadIdx.x; i < LOSS_BLOCKS; i += 256) a += g_partial[i];
    for (int o = 16; o > 0; o >>= 1) a += __shfl_down_sync(0xFFFFFFFFu, a, o);
    if ((threadIdx.x & 31) == 0) smem[threadIdx.x >> 5] = a;
    __syncthreads();
    if (threadIdx.x < 8) {
        double v = smem[threadIdx.x];
        for (int o = 4; o > 0; o >>= 1) v += __shfl_down_sync(0xFFu, v, o);
        if (threadIdx.x == 0) out[0] = (float)(v * (1.0 / (double)N_ELEMS));
    }
}

extern "C" void kernel_launch(void* const* d_in, const int* in_sizes, int n_in,
                              void* d_out, int out_size) {
    const float*  preds   = (const float*)d_in[0];
    const int4*   targets = (const int4*)d_in[1];
    float*        out     = (float*)d_out;

    k_presence<<<1024, 256>>>(targets);
    k_loss<<<LOSS_BLOCKS, LOSS_THREADS>>>((const float4*)preds);
    k_final<<<1, 256>>>(out);
}

// round 14
// speedup vs baseline: 1.1569x; 1.1569x over previous
#include <cuda_runtime.h>
#include <cuda_bf16.h>
#include <cstdint>

// preds:   (16, 19, 512, 512) float32  = 79,691,776 elems
// targets: (16, 1024, 1024)   labels in [0,19) (delivered as int32)
// grid_size = 16 -> 32x32 cells per batch, 16x16 px each
//
// k_presence: R12 verbatim.
// k_loss: block-contiguous regions streamed via cp.async.bulk (TMA engine):
//         each block owns 152 KB = 19 stages x 8 KB (4 rows/stage; a stage
//         never crosses a (b,c)-plane). One elected producer thread issues
//         one bulk copy + expect_tx per stage into a 4-deep smem ring;
//         consumers mbarrier-wait, read 2 float4s from private slots.
//         Per-stage sync = 1 mbarrier wait + 1 bar.sync per 8 KB (vs R13's
//         per-thread commit/wait storm). Math identical to R12.
// k_final: R12 verbatim.

#define N_ELEMS   79691776
#define N_CELLS   16384
#define LOSS_BLOCKS  2048
#define LOSS_THREADS 256
#define STAGES       4
#define STAGE_BYTES  8192
#define STAGE_ELEMS  2048                 // 4 rows of 512
#define BLK_STAGES   19                   // 19*8KB = 152KB/block
#define BLK_ELEMS    (BLK_STAGES * STAGE_ELEMS)   // 38912

__device__ unsigned g_masks[N_CELLS];
__device__ double   g_partial[LOSS_BLOCKS];

__device__ __forceinline__ float ex2_(float x) { float r; asm("ex2.approx.f32 %0, %1;" : "=f"(r) : "f"(x)); return r; }
__device__ __forceinline__ float lg2_(float x) { float r; asm("lg2.approx.f32 %0, %1;" : "=f"(r) : "f"(x)); return r; }

__device__ __forceinline__ unsigned smem_u32(const void* p) {
    unsigned a;
    asm("{ .reg .u64 t; cvta.to.shared.u64 t, %1; cvt.u32.u64 %0, t; }" : "=r"(a) : "l"(p));
    return a;
}
__device__ __forceinline__ void mbar_init(unsigned m, unsigned cnt) {
    asm volatile("mbarrier.init.shared.b64 [%0], %1;" :: "r"(m), "r"(cnt) : "memory");
}
__device__ __forceinline__ void mbar_expect_tx(unsigned m, unsigned bytes) {
    asm volatile("mbarrier.arrive.expect_tx.shared.b64 _, [%0], %1;" :: "r"(m), "r"(bytes) : "memory");
}
__device__ __forceinline__ void bulk_cp(unsigned dst, const void* src, unsigned bytes, unsigned m) {
    asm volatile("cp.async.bulk.shared::cta.global.mbarrier::complete_tx::bytes [%0], [%1], %2, [%3];"
                 :: "r"(dst), "l"(src), "r"(bytes), "r"(m) : "memory");
}
__device__ __forceinline__ void mbar_wait(unsigned m, unsigned parity) {
    asm volatile(
        "{ .reg .pred P;\n\t"
        "WL_%=: mbarrier.try_wait.parity.acquire.cta.shared::cta.b64 P, [%0], %1, 0x989680;\n\t"
        "@P bra WD_%=;\n\t"
        "bra WL_%=;\n\t"
        "WD_%=: }"
        :: "r"(m), "r"(parity) : "memory");
}

// ---------------------------------------------------------------------------
// Kernel 1: per-cell class-presence bitmask (stride-2 NN downsample).
// ---------------------------------------------------------------------------
__global__ void __launch_bounds__(256) k_presence(const int4* __restrict__ t4) {
    int gwarp = (blockIdx.x * blockDim.x + threadIdx.x) >> 5;
    int lane  = threadIdx.x & 31;
    int cellA = gwarp << 1;
    int bA    = cellA >> 10;
    int restA = cellA & 1023;
    int chA   = restA >> 5;
    int cwA   = restA & 31;

    int baseA = (bA << 18) + (chA << 13) + (cwA << 3);
    int baseB = baseA + 8;

    int4 qa[4], qb[4];
#pragma unroll
    for (int k = 0; k < 4; ++k) {
        int e = lane + (k << 5);
        int i = e >> 3, jj = e & 7;
        int roff = (i << 9) + jj;
        qa[k] = __ldg(&t4[baseA + roff]);
        qb[k] = __ldg(&t4[baseB + roff]);
    }
    unsigned mA = 0, mB = 0;
#pragma unroll
    for (int k = 0; k < 4; ++k) {
        mA |= (1u << (qa[k].x & 31)) | (1u << (qa[k].z & 31));
        mB |= (1u << (qb[k].x & 31)) | (1u << (qb[k].z & 31));
    }
    mA = __reduce_or_sync(0xFFFFFFFFu, mA);
    mB = __reduce_or_sync(0xFFFFFFFFu, mB);
    if (lane == 0) { g_masks[cellA] = mA; g_masks[cellA + 1] = mB; }
}

// BCE element: al += lg2(1+e^{-|x|}); aa += relu(se ? -x : x)
__device__ __forceinline__ void bce_acc(float x, unsigned sgn, float& al, float& aa) {
    float t = ex2_(fabsf(x) * -1.4426950408889634f);
    al += lg2_(1.0f + t);
    float y = __int_as_float(__float_as_int(x) ^ sgn);
    aa += fmaxf(y, 0.0f);
}

// ---------------------------------------------------------------------------
// Kernel 2: bulk-async pipelined streaming loss.
// ---------------------------------------------------------------------------
__global__ void __launch_bounds__(LOSS_THREADS) k_loss(const float* __restrict__ p) {
    __shared__ __align__(16) float  buf[STAGES][STAGE_ELEMS];
    __shared__ __align__(8) unsigned long long mbar[STAGES];
    __shared__ double smem[LOSS_THREADS / 32];

    const int tid = threadIdx.x;
    const int bid = blockIdx.x;
    const int e0  = bid * BLK_ELEMS;          // block's first element

    const unsigned mb0  = smem_u32(&mbar[0]);
    const unsigned sbuf = smem_u32(&buf[0][0]);

    if (tid == 0) {
#pragma unroll
        for (int s = 0; s < STAGES; ++s) mbar_init(mb0 + s * 8, 1);
    }
    __syncthreads();

    // prologue: stages 0..STAGES-2
    if (tid == 0) {
#pragma unroll
        for (int s = 0; s < STAGES - 1; ++s) {
            mbar_expect_tx(mb0 + s * 8, STAGE_BYTES);
            bulk_cp(sbuf + s * STAGE_BYTES, p + e0 + s * STAGE_ELEMS, STAGE_BYTES, mb0 + s * 8);
        }
    }

    float al0 = 0.f, al1 = 0.f, aa0 = 0.f, aa1 = 0.f;

    for (int k = 0; k < BLK_STAGES; ++k) {
        int slot = k & (STAGES - 1);
        // prefetch stage k+STAGES-1 (slot was drained at iter k-1; bar at end
        // of k-1 ordered all its readers before this issue)
        if (tid == 0 && k + STAGES - 1 < BLK_STAGES) {
            int fs = (k + STAGES - 1) & (STAGES - 1);
            mbar_expect_tx(mb0 + fs * 8, STAGE_BYTES);
            bulk_cp(sbuf + fs * STAGE_BYTES, p + e0 + (k + STAGES - 1) * STAGE_ELEMS,
                    STAGE_BYTES, mb0 + fs * 8);
        }
        mbar_wait(mb0 + slot * 8, (k >> 2) & 1);

        // geometry for this stage (single (b,c) plane; 4 rows)
        int g  = e0 + k * STAGE_ELEMS + (tid << 3);    // this thread's 8 elems
        int bc = g >> 18;
        int b  = bc / 19;
        int c  = bc - b * 19;
        int h  = (g >> 9) & 511;
        int w  = g & 511;
        unsigned mask = g_masks[(b << 10) + ((h >> 4) << 5) + (w >> 4)];
        unsigned sgn  = ((mask >> c) & 1u) << 31;

        const float4* s4 = reinterpret_cast<const float4*>(&buf[slot][tid << 3]);
        float4 v0 = s4[0];
        float4 v1 = s4[1];
        bce_acc(v0.x, sgn, al0, aa0); bce_acc(v0.y, sgn, al1, aa1);
        bce_acc(v0.z, sgn, al0, aa0); bce_acc(v0.w, sgn, al1, aa1);
        bce_acc(v1.x, sgn, al0, aa0); bce_acc(v1.y, sgn, al1, aa1);
        bce_acc(v1.z, sgn, al0, aa0); bce_acc(v1.w, sgn, al1, aa1);

        __syncthreads();   // all readers done with 'slot' before it is refilled
    }

    double acc = (double)(al0 + al1) * 0.6931471805599453 + (double)(aa0 + aa1);

    // deterministic block reduction
    for (int o = 16; o > 0; o >>= 1) acc += __shfl_down_sync(0xFFFFFFFFu, acc, o);
    if ((tid & 31) == 0) smem[tid >> 5] = acc;
    __syncthreads();
    if (tid < (LOSS_THREADS / 32)) {
        double a = smem[tid];
        for (int o = (LOSS_THREADS / 64); o > 0; o >>= 1)
            a += __shfl_down_sync(0xFFu, a, o);
        if (tid == 0) g_partial[bid] = a;
    }
}

// ---------------------------------------------------------------------------
// Kernel 3: final deterministic reduction -> mean.
// ---------------------------------------------------------------------------
__global__ void __launch_bounds__(256) k_final(float* __restrict__ out) {
    __shared__ double smem[8];
    double a = 0.0;
    for (int i = threadIdx.x; i < LOSS_BLOCKS; i += 256) a += g_partial[i];
    for (int o = 16; o > 0; o >>= 1) a += __shfl_down_sync(0xFFFFFFFFu, a, o);
    if ((threadIdx.x & 31) == 0) smem[threadIdx.x >> 5] = a;
    __syncthreads();
    if (threadIdx.x < 8) {
        double v = smem[threadIdx.x];
        for (int o = 4; o > 0; o >>= 1) v += __shfl_down_sync(0xFFu, v, o);
        if (threadIdx.x == 0) out[0] = (float)(v * (1.0 / (double)N_ELEMS));
    }
}

extern "C" void kernel_launch(void* const* d_in, const int* in_sizes, int n_in,
                              void* d_out, int out_size) {
    const float*  preds   = (const float*)d_in[0];
    const int4*   targets = (const int4*)d_in[1];
    float*        out     = (float*)d_out;

    k_presence<<<1024, 256>>>(targets);
    k_loss<<<LOSS_BLOCKS, LOSS_THREADS>>>(preds);
    k_final<<<1, 256>>>(out);
}

// round 15
// speedup vs baseline: 1.2557x; 1.0854x over previous
#include <cuda_runtime.h>
#include <cuda_bf16.h>

// preds:   (16, 19, 512, 512) float32  = 79,691,776 elems
// targets: (16, 1024, 1024)   labels in [0,19) (delivered as int32)
// grid_size = 16 -> 32x32 cells per batch, 16x16 px each
//
// Structure: R12's proven kernels + PDL overlap on the presence->loss edge.
//   k_presence: warp per 2 cells, MLP=8; triggers programmatic completion
//               right after mask stores.
//   k_loss:     launched with ProgrammaticStreamSerialization; runs E_STASH
//               mask-free iters (stashing per-iter sum(x)), then
//               cudaGridDependencySynchronize(), retro-fixes with -se*sum(x),
//               then the R12-verbatim masked loop for the remaining iters.
//   k_final:    R12 verbatim.

#define N_ELEMS   79691776
#define N4        (N_ELEMS / 4)          // 19,922,944 float4s
#define N_CELLS   16384
#define LOSS_BLOCKS  2048
#define LOSS_THREADS 256
#define LOSS_STRIDE  (LOSS_BLOCKS * LOSS_THREADS)   // N4/STRIDE = 38 exactly
#define LOSS_ITERS   38
#define E_STASH      6

__device__ unsigned g_masks[N_CELLS];
__device__ double   g_partial[LOSS_BLOCKS];

__device__ __forceinline__ float ex2_(float x) { float r; asm("ex2.approx.f32 %0, %1;" : "=f"(r) : "f"(x)); return r; }
__device__ __forceinline__ float lg2_(float x) { float r; asm("lg2.approx.f32 %0, %1;" : "=f"(r) : "f"(x)); return r; }

// ---------------------------------------------------------------------------
// Kernel 1: per-cell class-presence bitmask (stride-2 NN downsample).
// ---------------------------------------------------------------------------
__global__ void __launch_bounds__(256) k_presence(const int4* __restrict__ t4) {
    int gwarp = (blockIdx.x * blockDim.x + threadIdx.x) >> 5;  // 0..8191
    int lane  = threadIdx.x & 31;
    int cellA = gwarp << 1;
    int bA    = cellA >> 10;
    int restA = cellA & 1023;
    int chA   = restA >> 5;
    int cwA   = restA & 31;

    int baseA = (bA << 18) + (chA << 13) + (cwA << 3);
    int baseB = baseA + 8;

    int4 qa[4], qb[4];
#pragma unroll
    for (int k = 0; k < 4; ++k) {
        int e = lane + (k << 5);
        int i = e >> 3, jj = e & 7;
        int roff = (i << 9) + jj;
        qa[k] = __ldg(&t4[baseA + roff]);
        qb[k] = __ldg(&t4[baseB + roff]);
    }
    unsigned mA = 0, mB = 0;
#pragma unroll
    for (int k = 0; k < 4; ++k) {
        mA |= (1u << (qa[k].x & 31)) | (1u << (qa[k].z & 31));
        mB |= (1u << (qb[k].x & 31)) | (1u << (qb[k].z & 31));
    }
    mA = __reduce_or_sync(0xFFFFFFFFu, mA);
    mB = __reduce_or_sync(0xFFFFFFFFu, mB);
    if (lane == 0) { g_masks[cellA] = mA; g_masks[cellA + 1] = mB; }
    // allow the dependent k_loss grid to begin launching
    cudaTriggerProgrammaticLaunchCompletion();
}

// mask-free: al += lg2(1+e^{-|x|}); aa += relu(x)
__device__ __forceinline__ void bce_free(float x, float& al, float& aa) {
    al += lg2_(1.0f + ex2_(fabsf(x) * -1.4426950408889634f));
    aa += fmaxf(x, 0.0f);
}
// masked: al-term + relu(se ? -x : x)
__device__ __forceinline__ void bce_acc(float x, unsigned sgn, float& al, float& aa) {
    float t = ex2_(fabsf(x) * -1.4426950408889634f);
    al += lg2_(1.0f + t);
    float y = __int_as_float(__float_as_int(x) ^ sgn);
    aa += fmaxf(y, 0.0f);
}

// ---------------------------------------------------------------------------
// Kernel 2: streaming loss; overlaps with k_presence via PDL.
// ---------------------------------------------------------------------------
__global__ void __launch_bounds__(LOSS_THREADS) k_loss(const float4* __restrict__ p4) {
    int tid = blockIdx.x * blockDim.x + threadIdx.x;
    int lin = tid << 2;
    int w   = lin & 511;
    int h   = (lin >> 9) & 511;
    int cellhw = ((h >> 4) << 5) + (w >> 4);   // loop-invariant
    int bc0 = lin >> 18;                       // b*19+c at iter 0; +8 per iter

    float al0 = 0.f, al1 = 0.f, aa0 = 0.f, aa1 = 0.f;

    // ---- phase 1: mask-free iters while k_presence drains ----
    float sx[E_STASH];
#pragma unroll
    for (int k = 0; k < E_STASH; ++k) {
        float4 v = __ldcs(p4 + tid + k * LOSS_STRIDE);
        bce_free(v.x, al0, aa0); bce_free(v.y, al1, aa1);
        bce_free(v.z, al0, aa0); bce_free(v.w, al1, aa1);
        sx[k] = (v.x + v.y) + (v.z + v.w);
    }

    // ---- wait for k_presence's writes to be visible ----
    cudaGridDependencySynchronize();

    // retro-fix stashed iters:  aa -= se_k * sum_x_k
#pragma unroll
    for (int k = 0; k < E_STASH; ++k) {
        int bc = bc0 + (k << 3);
        int b  = bc / 19;
        int c  = bc - b * 19;
        float se = (float)((g_masks[(b << 10) + cellhw] >> c) & 1u);
        aa0 = fmaf(-se, sx[k], aa0);
    }

    // ---- phase 2: masked loop (R12 verbatim form) ----
#pragma unroll 2
    for (int k = E_STASH; k < LOSS_ITERS; ++k) {
        float4 v = __ldcs(p4 + tid + k * LOSS_STRIDE);
        int bc = bc0 + (k << 3);
        int b  = bc / 19;
        int c  = bc - b * 19;
        unsigned mask = g_masks[(b << 10) + cellhw];
        unsigned sgn  = ((mask >> c) & 1u) << 31;
        bce_acc(v.x, sgn, al0, aa0);
        bce_acc(v.y, sgn, al1, aa1);
        bce_acc(v.z, sgn, al0, aa0);
        bce_acc(v.w, sgn, al1, aa1);
    }

    double acc = (double)(al0 + al1) * 0.6931471805599453 + (double)(aa0 + aa1);

    // deterministic block reduction
    __shared__ double smem[LOSS_THREADS / 32];
    for (int o = 16; o > 0; o >>= 1) acc += __shfl_down_sync(0xFFFFFFFFu, acc, o);
    if ((threadIdx.x & 31) == 0) smem[threadIdx.x >> 5] = acc;
    __syncthreads();
    if (threadIdx.x < (LOSS_THREADS / 32)) {
        double a = smem[threadIdx.x];
        for (int o = (LOSS_THREADS / 64); o > 0; o >>= 1)
            a += __shfl_down_sync(0xFFu, a, o);
        if (threadIdx.x == 0) g_partial[blockIdx.x] = a;
    }
}

// ---------------------------------------------------------------------------
// Kernel 3: final deterministic reduction -> mean.
// ---------------------------------------------------------------------------
__global__ void __launch_bounds__(256) k_final(float* __restrict__ out) {
    __shared__ double smem[8];
    double a = 0.0;
    for (int i = threadIdx.x; i < LOSS_BLOCKS; i += 256) a += g_partial[i];
    for (int o = 16; o > 0; o >>= 1) a += __shfl_down_sync(0xFFFFFFFFu, a, o);
    if ((threadIdx.x & 31) == 0) smem[threadIdx.x >> 5] = a;
    __syncthreads();
    if (threadIdx.x < 8) {
        double v = smem[threadIdx.x];
        for (int o = 4; o > 0; o >>= 1) v += __shfl_down_sync(0xFFu, v, o);
        if (threadIdx.x == 0) out[0] = (float)(v * (1.0 / (double)N_ELEMS));
    }
}

extern "C" void kernel_launch(void* const* d_in, const int* in_sizes, int n_in,
                              void* d_out, int out_size) {
    const float*  preds   = (const float*)d_in[0];
    const int4*   targets = (const int4*)d_in[1];
    float*        out     = (float*)d_out;

    k_presence<<<1024, 256>>>(targets);

    // k_loss with programmatic dependent launch: may begin while k_presence
    // is still resident; correctness gated by cudaGridDependencySynchronize.
    cudaLaunchConfig_t cfg = {};
    cfg.gridDim  = dim3(LOSS_BLOCKS);
    cfg.blockDim = dim3(LOSS_THREADS);
    cfg.stream   = 0;
    cudaLaunchAttribute attrs[1];
    attrs[0].id = cudaLaunchAttributeProgrammaticStreamSerialization;
    attrs[0].val.programmaticStreamSerializationAllowed = 1;
    cfg.attrs    = attrs;
    cfg.numAttrs = 1;
    cudaLaunchKernelEx(&cfg, k_loss, (const float4*)preds);

    k_final<<<1, 256>>>(out);
}